// round 12
// baseline (speedup 1.0000x reference)
#include <cuda_runtime.h>
#include <cstdint>

// Problem constants (match reference_code)
#define N_USER   100000
#define N_ITEM   50000
#define NTOT     150000
#define D        64
#define NNZ_CNT  4000000
#define BATCH    2048
#define NEGS     8192
#define NOUT     (BATCH + BATCH + NEGS)   // 12288 output slots
#define BM_WORDS ((NTOT + 31) / 32)       // 4688
#define MAXK     96                       // bucket capacity (lambda=26.7)

#define FULLMASK 0xffffffffu
#define NNZ_PER_BLOCK 8192                // 256 thr * 32 nnz

// Scratch (device globals). Everything read each launch is re-initialized
// each launch (bitmap, counts, id entries for flagged rows), so graph
// replays are self-consistent. Stale g_id/g_bkt entries are never read.
__device__ unsigned g_bm[BM_WORDS];             // 19 KB row bitmap
__device__ int      g_id[NTOT];                 // row -> winning slot id
__device__ int      g_rowof[NOUT];              // slot -> row
__device__ int      g_cnt[NOUT];                // hits per slot id
__device__ float2   g_bkt[(size_t)NOUT * MAXK]; // {col_bits, val} ~9.4 MB

// ---------------------------------------------------------------------------
// Kernel 1: clear bitmap + per-id hit counters
// ---------------------------------------------------------------------------
__global__ void k_clear()
{
    int i = blockIdx.x * blockDim.x + threadIdx.x;
    if (i < BM_WORDS) g_bm[i] = 0u;
    if (i < NOUT)     g_cnt[i] = 0;
}

// ---------------------------------------------------------------------------
// Kernel 2: resolve slot->row, set bitmap bit, write row->slot winner map.
// Duplicate rows: plain-store race picks an arbitrary winner; output value
// is winner-independent (fixed up by k_fixdup).
// ---------------------------------------------------------------------------
__global__ void k_mark(const int* __restrict__ users,
                       const int* __restrict__ pos,
                       const int* __restrict__ neg)
{
    int slot = blockIdx.x * blockDim.x + threadIdx.x;
    if (slot >= NOUT) return;

    int row;
    if (slot < BATCH)            row = users[slot];
    else if (slot < 2 * BATCH)   row = N_USER + pos[slot - BATCH];
    else                         row = N_USER + neg[slot - 2 * BATCH];

    g_rowof[slot] = row;
    g_id[row]     = slot;
    atomicOr(&g_bm[row >> 5], 1u << (row & 31));
}

// ---------------------------------------------------------------------------
// Kernel 3: fill buckets. 8192 nnz per block (32/thread) to amortize the
// SMEM bitmap staging. Hits: id lookup, one atomicAdd for position, 8B store.
// ---------------------------------------------------------------------------
__global__ void k_fill(const int*   __restrict__ rows,
                       const int*   __restrict__ cols,
                       const float* __restrict__ vals)
{
    __shared__ unsigned s_bm[BM_WORDS];
    const int tid = threadIdx.x;
#pragma unroll
    for (int i = 0; i < BM_WORDS / 256 + 1; i++) {
        int w = i * 256 + tid;
        if (w < BM_WORDS) s_bm[w] = g_bm[w];
    }
    __syncthreads();

    const long myBase = (long)blockIdx.x * NNZ_PER_BLOCK + (long)tid * 32;
    if (myBase >= NNZ_CNT) return;   // NNZ % 32 == 0: chunk all-in or all-out

    int r[32];
#pragma unroll
    for (int i = 0; i < 8; i++) {
        int4 a = *reinterpret_cast<const int4*>(rows + myBase + i * 4);
        r[i*4+0]=a.x; r[i*4+1]=a.y; r[i*4+2]=a.z; r[i*4+3]=a.w;
    }

    unsigned m = 0;
#pragma unroll
    for (int j = 0; j < 32; j++)
        if ((s_bm[r[j] >> 5] >> (r[j] & 31)) & 1u) m |= (1u << j);

    while (m) {
        int j = __ffs(m) - 1;
        m &= m - 1;
        int id = g_id[r[j]];
        int p  = atomicAdd(&g_cnt[id], 1);
        if (p < MAXK) {
            float2 rec;
            rec.x = __int_as_float(cols[myBase + j]);
            rec.y = vals[myBase + j];
            g_bkt[(size_t)id * MAXK + p] = rec;
        }
    }
}

// ---------------------------------------------------------------------------
// Kernel 4: accumulate. ONE WARP per slot; each lane owns 2 floats (float2).
// Hits unrolled x4 -> 4 independent gathers in flight per lane.
// out[id] = 0.75 * (e0[row]/3 + sum_h v_h * e0[c_h])
// ---------------------------------------------------------------------------
__global__ void k_accum(const float* __restrict__ ue,
                        const float* __restrict__ ie,
                        float* __restrict__ out)
{
    const int lane = threadIdx.x & 31;
    const int id   = (blockIdx.x * blockDim.x + threadIdx.x) >> 5;
    if (id >= NOUT) return;

    const int row = g_rowof[id];
    int cnt = g_cnt[id];
    if (cnt > MAXK) cnt = MAXK;

    const float* seed = (row < N_USER) ? (ue + (size_t)row * D)
                                       : (ie + (size_t)(row - N_USER) * D);
    float2 A = reinterpret_cast<const float2*>(seed)[lane];
    const float k3 = 1.0f / 3.0f;
    A.x *= k3; A.y *= k3;

    const float4* bkt4 = reinterpret_cast<const float4*>(g_bkt + (size_t)id * MAXK);

    int h = 0;
    for (; h + 3 < cnt; h += 4) {
        // 4 records = 2 float4 broadcast loads
        float4 rA = bkt4[h >> 1];
        float4 rB = bkt4[(h >> 1) + 1];
        int   c0 = __float_as_int(rA.x);  float v0 = rA.y;
        int   c1 = __float_as_int(rA.z);  float v1 = rA.w;
        int   c2 = __float_as_int(rB.x);  float v2 = rB.y;
        int   c3 = __float_as_int(rB.z);  float v3 = rB.w;

        const float* p0 = (c0 < N_USER) ? (ue + (size_t)c0 * D) : (ie + (size_t)(c0 - N_USER) * D);
        const float* p1 = (c1 < N_USER) ? (ue + (size_t)c1 * D) : (ie + (size_t)(c1 - N_USER) * D);
        const float* p2 = (c2 < N_USER) ? (ue + (size_t)c2 * D) : (ie + (size_t)(c2 - N_USER) * D);
        const float* p3 = (c3 < N_USER) ? (ue + (size_t)c3 * D) : (ie + (size_t)(c3 - N_USER) * D);

        float2 e0 = reinterpret_cast<const float2*>(p0)[lane];
        float2 e1 = reinterpret_cast<const float2*>(p1)[lane];
        float2 e2 = reinterpret_cast<const float2*>(p2)[lane];
        float2 e3 = reinterpret_cast<const float2*>(p3)[lane];

        A.x += e0.x * v0;  A.y += e0.y * v0;
        A.x += e1.x * v1;  A.y += e1.y * v1;
        A.x += e2.x * v2;  A.y += e2.y * v2;
        A.x += e3.x * v3;  A.y += e3.y * v3;
    }
    for (; h < cnt; h++) {
        float2 rec = g_bkt[(size_t)id * MAXK + h];
        int   c = __float_as_int(rec.x);  float v = rec.y;
        const float* p = (c < N_USER) ? (ue + (size_t)c * D) : (ie + (size_t)(c - N_USER) * D);
        float2 e = reinterpret_cast<const float2*>(p)[lane];
        A.x += e.x * v;  A.y += e.y * v;
    }

    A.x *= 0.75f;  A.y *= 0.75f;
    reinterpret_cast<float2*>(out + (size_t)id * D)[lane] = A;
}

// ---------------------------------------------------------------------------
// Kernel 5: fix duplicate slots — copy winner's output row.
// ---------------------------------------------------------------------------
__global__ void k_fixdup(float* __restrict__ out)
{
    int tid  = blockIdx.x * blockDim.x + threadIdx.x;
    int slot = tid >> 4;
    int l16  = tid & 15;
    if (slot >= NOUT) return;

    int row = g_rowof[slot];
    int w   = g_id[row];
    if (w == slot) return;

    float4 v = reinterpret_cast<const float4*>(out + (size_t)w * D)[l16];
    reinterpret_cast<float4*>(out + (size_t)slot * D)[l16] = v;
}

// ---------------------------------------------------------------------------
// Launch
// ---------------------------------------------------------------------------
extern "C" void kernel_launch(void* const* d_in, const int* in_sizes, int n_in,
                              void* d_out, int out_size)
{
    const int*   users = (const int*)  d_in[0];
    const int*   pos   = (const int*)  d_in[1];
    const int*   neg   = (const int*)  d_in[2];
    const float* ue    = (const float*)d_in[5];
    const float* ie    = (const float*)d_in[6];
    const int*   arow  = (const int*)  d_in[7];
    const int*   acol  = (const int*)  d_in[8];
    const float* aval  = (const float*)d_in[9];
    float*       out   = (float*)d_out;

    k_clear<<<(NOUT + 255) / 256, 256>>>();

    k_mark<<<(NOUT + 255) / 256, 256>>>(users, pos, neg);

    {
        const int blocks = (NNZ_CNT + NNZ_PER_BLOCK - 1) / NNZ_PER_BLOCK; // 489
        k_fill<<<blocks, 256>>>(arow, acol, aval);
    }

    // one warp per slot: 12288 warps = 1536 blocks x 8 warps
    k_accum<<<(NOUT * 32 + 255) / 256, 256>>>(ue, ie, out);

    k_fixdup<<<(NOUT * 16 + 255) / 256, 256>>>(out);
}

// round 13
// speedup vs baseline: 1.0012x; 1.0012x over previous
#include <cuda_runtime.h>
#include <cstdint>

// Problem constants (match reference_code)
#define N_USER   100000
#define N_ITEM   50000
#define NTOT     150000
#define D        64
#define NNZ_CNT  4000000
#define BATCH    2048
#define NEGS     8192
#define NOUT     (BATCH + BATCH + NEGS)   // 12288 output slots
#define BM_WORDS ((NTOT + 31) / 32)       // 4688
#define MAXK     96                       // bucket capacity (lambda=26.7)

#define FULLMASK 0xffffffffu
#define NNZ_PER_BLOCK 8192                // 256 thr * 32 nnz

// Scratch (device globals). Everything read each launch is re-initialized
// each launch (bitmap, counts, id entries for flagged rows), so graph
// replays are self-consistent. Stale g_id/g_bkt entries are never read.
__device__ unsigned g_bm[BM_WORDS];             // 19 KB row bitmap
__device__ int      g_id[NTOT];                 // row -> winning slot id
__device__ int      g_rowof[NOUT];              // slot -> row
__device__ int      g_cnt[NOUT];                // hits per slot id
__device__ float2   g_bkt[(size_t)NOUT * MAXK]; // {col_bits, val} ~9.4 MB

// ---------------------------------------------------------------------------
// Kernel 1: clear bitmap + per-id hit counters
// ---------------------------------------------------------------------------
__global__ void k_clear()
{
    int i = blockIdx.x * blockDim.x + threadIdx.x;
    if (i < BM_WORDS) g_bm[i] = 0u;
    if (i < NOUT)     g_cnt[i] = 0;
}

// ---------------------------------------------------------------------------
// Kernel 2: resolve slot->row, set bitmap bit, write row->slot winner map.
// Duplicate rows: plain-store race picks an arbitrary winner; output value
// is winner-independent (fixed up by k_fixdup).
// ---------------------------------------------------------------------------
__global__ void k_mark(const int* __restrict__ users,
                       const int* __restrict__ pos,
                       const int* __restrict__ neg)
{
    int slot = blockIdx.x * blockDim.x + threadIdx.x;
    if (slot >= NOUT) return;

    int row;
    if (slot < BATCH)            row = users[slot];
    else if (slot < 2 * BATCH)   row = N_USER + pos[slot - BATCH];
    else                         row = N_USER + neg[slot - 2 * BATCH];

    g_rowof[slot] = row;
    g_id[row]     = slot;
    atomicOr(&g_bm[row >> 5], 1u << (row & 31));
}

// ---------------------------------------------------------------------------
// Kernel 3: fill buckets. 8192 nnz per block (32/thread) to amortize the
// SMEM bitmap staging. Hits: id lookup, one atomicAdd for position, 8B store.
// ---------------------------------------------------------------------------
__global__ void k_fill(const int*   __restrict__ rows,
                       const int*   __restrict__ cols,
                       const float* __restrict__ vals)
{
    __shared__ unsigned s_bm[BM_WORDS];
    const int tid = threadIdx.x;
#pragma unroll
    for (int i = 0; i < BM_WORDS / 256 + 1; i++) {
        int w = i * 256 + tid;
        if (w < BM_WORDS) s_bm[w] = g_bm[w];
    }
    __syncthreads();

    const long myBase = (long)blockIdx.x * NNZ_PER_BLOCK + (long)tid * 32;
    if (myBase >= NNZ_CNT) return;   // NNZ % 32 == 0: chunk all-in or all-out

    int r[32];
#pragma unroll
    for (int i = 0; i < 8; i++) {
        int4 a = *reinterpret_cast<const int4*>(rows + myBase + i * 4);
        r[i*4+0]=a.x; r[i*4+1]=a.y; r[i*4+2]=a.z; r[i*4+3]=a.w;
    }

    unsigned m = 0;
#pragma unroll
    for (int j = 0; j < 32; j++)
        if ((s_bm[r[j] >> 5] >> (r[j] & 31)) & 1u) m |= (1u << j);

    while (m) {
        int j = __ffs(m) - 1;
        m &= m - 1;
        int id = g_id[r[j]];
        int p  = atomicAdd(&g_cnt[id], 1);
        if (p < MAXK) {
            float2 rec;
            rec.x = __int_as_float(cols[myBase + j]);
            rec.y = vals[myBase + j];
            g_bkt[(size_t)id * MAXK + p] = rec;
        }
    }
}

// ---------------------------------------------------------------------------
// Kernel 4: accumulate. ONE WARP per slot; each lane owns 2 floats (float2).
// Hits unrolled x4 -> 4 independent gathers in flight per lane.
// out[id] = 0.75 * (e0[row]/3 + sum_h v_h * e0[c_h])
// ---------------------------------------------------------------------------
__global__ void k_accum(const float* __restrict__ ue,
                        const float* __restrict__ ie,
                        float* __restrict__ out)
{
    const int lane = threadIdx.x & 31;
    const int id   = (blockIdx.x * blockDim.x + threadIdx.x) >> 5;
    if (id >= NOUT) return;

    const int row = g_rowof[id];
    int cnt = g_cnt[id];
    if (cnt > MAXK) cnt = MAXK;

    const float* seed = (row < N_USER) ? (ue + (size_t)row * D)
                                       : (ie + (size_t)(row - N_USER) * D);
    float2 A = reinterpret_cast<const float2*>(seed)[lane];
    const float k3 = 1.0f / 3.0f;
    A.x *= k3; A.y *= k3;

    const float4* bkt4 = reinterpret_cast<const float4*>(g_bkt + (size_t)id * MAXK);

    int h = 0;
    for (; h + 3 < cnt; h += 4) {
        // 4 records = 2 float4 broadcast loads
        float4 rA = bkt4[h >> 1];
        float4 rB = bkt4[(h >> 1) + 1];
        int   c0 = __float_as_int(rA.x);  float v0 = rA.y;
        int   c1 = __float_as_int(rA.z);  float v1 = rA.w;
        int   c2 = __float_as_int(rB.x);  float v2 = rB.y;
        int   c3 = __float_as_int(rB.z);  float v3 = rB.w;

        const float* p0 = (c0 < N_USER) ? (ue + (size_t)c0 * D) : (ie + (size_t)(c0 - N_USER) * D);
        const float* p1 = (c1 < N_USER) ? (ue + (size_t)c1 * D) : (ie + (size_t)(c1 - N_USER) * D);
        const float* p2 = (c2 < N_USER) ? (ue + (size_t)c2 * D) : (ie + (size_t)(c2 - N_USER) * D);
        const float* p3 = (c3 < N_USER) ? (ue + (size_t)c3 * D) : (ie + (size_t)(c3 - N_USER) * D);

        float2 e0 = reinterpret_cast<const float2*>(p0)[lane];
        float2 e1 = reinterpret_cast<const float2*>(p1)[lane];
        float2 e2 = reinterpret_cast<const float2*>(p2)[lane];
        float2 e3 = reinterpret_cast<const float2*>(p3)[lane];

        A.x += e0.x * v0;  A.y += e0.y * v0;
        A.x += e1.x * v1;  A.y += e1.y * v1;
        A.x += e2.x * v2;  A.y += e2.y * v2;
        A.x += e3.x * v3;  A.y += e3.y * v3;
    }
    for (; h < cnt; h++) {
        float2 rec = g_bkt[(size_t)id * MAXK + h];
        int   c = __float_as_int(rec.x);  float v = rec.y;
        const float* p = (c < N_USER) ? (ue + (size_t)c * D) : (ie + (size_t)(c - N_USER) * D);
        float2 e = reinterpret_cast<const float2*>(p)[lane];
        A.x += e.x * v;  A.y += e.y * v;
    }

    A.x *= 0.75f;  A.y *= 0.75f;
    reinterpret_cast<float2*>(out + (size_t)id * D)[lane] = A;
}

// ---------------------------------------------------------------------------
// Kernel 5: fix duplicate slots — copy winner's output row.
// ---------------------------------------------------------------------------
__global__ void k_fixdup(float* __restrict__ out)
{
    int tid  = blockIdx.x * blockDim.x + threadIdx.x;
    int slot = tid >> 4;
    int l16  = tid & 15;
    if (slot >= NOUT) return;

    int row = g_rowof[slot];
    int w   = g_id[row];
    if (w == slot) return;

    float4 v = reinterpret_cast<const float4*>(out + (size_t)w * D)[l16];
    reinterpret_cast<float4*>(out + (size_t)slot * D)[l16] = v;
}

// ---------------------------------------------------------------------------
// Launch
// ---------------------------------------------------------------------------
extern "C" void kernel_launch(void* const* d_in, const int* in_sizes, int n_in,
                              void* d_out, int out_size)
{
    const int*   users = (const int*)  d_in[0];
    const int*   pos   = (const int*)  d_in[1];
    const int*   neg   = (const int*)  d_in[2];
    const float* ue    = (const float*)d_in[5];
    const float* ie    = (const float*)d_in[6];
    const int*   arow  = (const int*)  d_in[7];
    const int*   acol  = (const int*)  d_in[8];
    const float* aval  = (const float*)d_in[9];
    float*       out   = (float*)d_out;

    k_clear<<<(NOUT + 255) / 256, 256>>>();

    k_mark<<<(NOUT + 255) / 256, 256>>>(users, pos, neg);

    {
        const int blocks = (NNZ_CNT + NNZ_PER_BLOCK - 1) / NNZ_PER_BLOCK; // 489
        k_fill<<<blocks, 256>>>(arow, acol, aval);
    }

    // one warp per slot: 12288 warps = 1536 blocks x 8 warps
    k_accum<<<(NOUT * 32 + 255) / 256, 256>>>(ue, ie, out);

    k_fixdup<<<(NOUT * 16 + 255) / 256, 256>>>(out);
}

// round 14
// speedup vs baseline: 1.0329x; 1.0316x over previous
#include <cuda_runtime.h>
#include <cstdint>

// Problem constants (match reference_code)
#define N_USER   100000
#define N_ITEM   50000
#define NTOT     150000
#define D        64
#define NNZ_CNT  4000000
#define BATCH    2048
#define NEGS     8192
#define NOUT     (BATCH + BATCH + NEGS)   // 12288 output slots
#define BM_WORDS ((NTOT + 31) / 32)       // 4688
#define MAXK     96                       // bucket capacity (lambda=26.7)

#define FULLMASK 0xffffffffu
#define NNZ_PER_BLOCK 8192                // 256 thr * 32 nnz

// Scratch (device globals). Everything read each launch is re-initialized
// each launch (bitmap, counts, id entries for flagged rows), so graph
// replays are self-consistent. Stale g_id/g_bkt entries are never read.
__device__ unsigned g_bm[BM_WORDS];             // 19 KB row bitmap
__device__ int      g_id[NTOT];                 // row -> winning slot id
__device__ int      g_rowof[NOUT];              // slot -> row
__device__ int      g_cnt[NOUT];                // hits per slot id
__device__ float2   g_bkt[(size_t)NOUT * MAXK]; // {col_bits, val} ~9.4 MB

// ---------------------------------------------------------------------------
// Kernel 1: clear bitmap + per-id hit counters
// ---------------------------------------------------------------------------
__global__ void k_clear()
{
    int i = blockIdx.x * blockDim.x + threadIdx.x;
    if (i < BM_WORDS) g_bm[i] = 0u;
    if (i < NOUT)     g_cnt[i] = 0;
}

// ---------------------------------------------------------------------------
// Kernel 2: resolve slot->row, set bitmap bit, write row->slot winner map.
// Duplicate rows: plain-store race picks an arbitrary winner; output value
// is winner-independent (fixed up by k_fixdup).
// ---------------------------------------------------------------------------
__global__ void k_mark(const int* __restrict__ users,
                       const int* __restrict__ pos,
                       const int* __restrict__ neg)
{
    int slot = blockIdx.x * blockDim.x + threadIdx.x;
    if (slot >= NOUT) return;

    int row;
    if (slot < BATCH)            row = users[slot];
    else if (slot < 2 * BATCH)   row = N_USER + pos[slot - BATCH];
    else                         row = N_USER + neg[slot - 2 * BATCH];

    g_rowof[slot] = row;
    g_id[row]     = slot;
    atomicOr(&g_bm[row >> 5], 1u << (row & 31));
}

// ---------------------------------------------------------------------------
// Kernel 3: fill buckets. 8192 nnz per block (32/thread) to amortize the
// SMEM bitmap staging. Hits: id lookup, one atomicAdd for position, 8B store.
// ---------------------------------------------------------------------------
__global__ void k_fill(const int*   __restrict__ rows,
                       const int*   __restrict__ cols,
                       const float* __restrict__ vals)
{
    __shared__ unsigned s_bm[BM_WORDS];
    const int tid = threadIdx.x;
#pragma unroll
    for (int i = 0; i < BM_WORDS / 256 + 1; i++) {
        int w = i * 256 + tid;
        if (w < BM_WORDS) s_bm[w] = g_bm[w];
    }
    __syncthreads();

    const long myBase = (long)blockIdx.x * NNZ_PER_BLOCK + (long)tid * 32;
    if (myBase >= NNZ_CNT) return;   // NNZ % 32 == 0: chunk all-in or all-out

    int r[32];
#pragma unroll
    for (int i = 0; i < 8; i++) {
        int4 a = *reinterpret_cast<const int4*>(rows + myBase + i * 4);
        r[i*4+0]=a.x; r[i*4+1]=a.y; r[i*4+2]=a.z; r[i*4+3]=a.w;
    }

    unsigned m = 0;
#pragma unroll
    for (int j = 0; j < 32; j++)
        if ((s_bm[r[j] >> 5] >> (r[j] & 31)) & 1u) m |= (1u << j);

    while (m) {
        int j = __ffs(m) - 1;
        m &= m - 1;
        int id = g_id[r[j]];
        int p  = atomicAdd(&g_cnt[id], 1);
        if (p < MAXK) {
            float2 rec;
            rec.x = __int_as_float(cols[myBase + j]);
            rec.y = vals[myBase + j];
            g_bkt[(size_t)id * MAXK + p] = rec;
        }
    }
}

// ---------------------------------------------------------------------------
// Kernel 4: accumulate. ONE WARP per slot; each lane owns 2 floats (float2).
// Hits unrolled x4 -> 4 independent gathers in flight per lane.
// out[id] = 0.75 * (e0[row]/3 + sum_h v_h * e0[c_h])
// ---------------------------------------------------------------------------
__global__ void k_accum(const float* __restrict__ ue,
                        const float* __restrict__ ie,
                        float* __restrict__ out)
{
    const int lane = threadIdx.x & 31;
    const int id   = (blockIdx.x * blockDim.x + threadIdx.x) >> 5;
    if (id >= NOUT) return;

    const int row = g_rowof[id];
    int cnt = g_cnt[id];
    if (cnt > MAXK) cnt = MAXK;

    const float* seed = (row < N_USER) ? (ue + (size_t)row * D)
                                       : (ie + (size_t)(row - N_USER) * D);
    float2 A = reinterpret_cast<const float2*>(seed)[lane];
    const float k3 = 1.0f / 3.0f;
    A.x *= k3; A.y *= k3;

    const float4* bkt4 = reinterpret_cast<const float4*>(g_bkt + (size_t)id * MAXK);

    int h = 0;
    for (; h + 3 < cnt; h += 4) {
        // 4 records = 2 float4 broadcast loads
        float4 rA = bkt4[h >> 1];
        float4 rB = bkt4[(h >> 1) + 1];
        int   c0 = __float_as_int(rA.x);  float v0 = rA.y;
        int   c1 = __float_as_int(rA.z);  float v1 = rA.w;
        int   c2 = __float_as_int(rB.x);  float v2 = rB.y;
        int   c3 = __float_as_int(rB.z);  float v3 = rB.w;

        const float* p0 = (c0 < N_USER) ? (ue + (size_t)c0 * D) : (ie + (size_t)(c0 - N_USER) * D);
        const float* p1 = (c1 < N_USER) ? (ue + (size_t)c1 * D) : (ie + (size_t)(c1 - N_USER) * D);
        const float* p2 = (c2 < N_USER) ? (ue + (size_t)c2 * D) : (ie + (size_t)(c2 - N_USER) * D);
        const float* p3 = (c3 < N_USER) ? (ue + (size_t)c3 * D) : (ie + (size_t)(c3 - N_USER) * D);

        float2 e0 = reinterpret_cast<const float2*>(p0)[lane];
        float2 e1 = reinterpret_cast<const float2*>(p1)[lane];
        float2 e2 = reinterpret_cast<const float2*>(p2)[lane];
        float2 e3 = reinterpret_cast<const float2*>(p3)[lane];

        A.x += e0.x * v0;  A.y += e0.y * v0;
        A.x += e1.x * v1;  A.y += e1.y * v1;
        A.x += e2.x * v2;  A.y += e2.y * v2;
        A.x += e3.x * v3;  A.y += e3.y * v3;
    }
    for (; h < cnt; h++) {
        float2 rec = g_bkt[(size_t)id * MAXK + h];
        int   c = __float_as_int(rec.x);  float v = rec.y;
        const float* p = (c < N_USER) ? (ue + (size_t)c * D) : (ie + (size_t)(c - N_USER) * D);
        float2 e = reinterpret_cast<const float2*>(p)[lane];
        A.x += e.x * v;  A.y += e.y * v;
    }

    A.x *= 0.75f;  A.y *= 0.75f;
    reinterpret_cast<float2*>(out + (size_t)id * D)[lane] = A;
}

// ---------------------------------------------------------------------------
// Kernel 5: fix duplicate slots — copy winner's output row.
// ---------------------------------------------------------------------------
__global__ void k_fixdup(float* __restrict__ out)
{
    int tid  = blockIdx.x * blockDim.x + threadIdx.x;
    int slot = tid >> 4;
    int l16  = tid & 15;
    if (slot >= NOUT) return;

    int row = g_rowof[slot];
    int w   = g_id[row];
    if (w == slot) return;

    float4 v = reinterpret_cast<const float4*>(out + (size_t)w * D)[l16];
    reinterpret_cast<float4*>(out + (size_t)slot * D)[l16] = v;
}

// ---------------------------------------------------------------------------
// Launch
// ---------------------------------------------------------------------------
extern "C" void kernel_launch(void* const* d_in, const int* in_sizes, int n_in,
                              void* d_out, int out_size)
{
    const int*   users = (const int*)  d_in[0];
    const int*   pos   = (const int*)  d_in[1];
    const int*   neg   = (const int*)  d_in[2];
    const float* ue    = (const float*)d_in[5];
    const float* ie    = (const float*)d_in[6];
    const int*   arow  = (const int*)  d_in[7];
    const int*   acol  = (const int*)  d_in[8];
    const float* aval  = (const float*)d_in[9];
    float*       out   = (float*)d_out;

    k_clear<<<(NOUT + 255) / 256, 256>>>();

    k_mark<<<(NOUT + 255) / 256, 256>>>(users, pos, neg);

    {
        const int blocks = (NNZ_CNT + NNZ_PER_BLOCK - 1) / NNZ_PER_BLOCK; // 489
        k_fill<<<blocks, 256>>>(arow, acol, aval);
    }

    // one warp per slot: 12288 warps = 1536 blocks x 8 warps
    k_accum<<<(NOUT * 32 + 255) / 256, 256>>>(ue, ie, out);

    k_fixdup<<<(NOUT * 16 + 255) / 256, 256>>>(out);
}